// round 10
// baseline (speedup 1.0000x reference)
#include <cuda_runtime.h>
#include <math.h>

#define BB      16
#define NA      286
#define NAP     288       // padded atom count (multiple of 8)
#define HID     150
#define FF      512
#define RADIUS_F 3.0f
#define MT      512       // table knots per cloud
#define PTS     4         // points per build block
#define CH      10        // k-chunk (prefetch depth) in build

// ---------------- scratch (device globals; no allocation allowed) ----------
__device__ __align__(16) float g_feats0[BB*NA*4];
__device__ __align__(16) float g_f1[BB*NA*4];
__device__ __align__(16) float g_f2[BB*NA*4];
// paired-knot table: row i holds {K_i[q][0..3], K_{i+1}[q][0..3]} for q=0..3 -> 32 floats.
// Row MT is the zero sentinel (never written; device globals are zero-initialized).
__device__ __align__(16) float g_tab2[2][(MT+1)*32];
__device__ float g_nbinv[BB*NA];
__device__ float g_h[BB*FF];

__device__ __forceinline__ float sp5(float x) {
    float z = 5.0f * x;
    return (fmaxf(z, 0.0f) + log1pf(expf(-fabsf(z)))) * 0.2f;
}
__device__ __forceinline__ float softplus1(float x) {
    return fmaxf(x, 0.0f) + log1pf(expf(-fabsf(x)));
}

// ---- packed f32x2 helpers (sm_103a) --------------------------------------
__device__ __forceinline__ unsigned long long f2_pack(float lo, float hi) {
    unsigned long long r;
    asm("mov.b64 %0, {%1, %2};" : "=l"(r) : "f"(lo), "f"(hi));
    return r;
}
__device__ __forceinline__ void f2_unpack(float& lo, float& hi, unsigned long long v) {
    asm("mov.b64 {%0, %1}, %2;" : "=f"(lo), "=f"(hi) : "l"(v));
}
__device__ __forceinline__ unsigned long long f2_mul(unsigned long long a, unsigned long long b) {
    unsigned long long r;
    asm("mul.rn.f32x2 %0, %1, %2;" : "=l"(r) : "l"(a), "l"(b));
    return r;
}
__device__ __forceinline__ unsigned long long f2_fma(unsigned long long a, unsigned long long b,
                                                     unsigned long long c) {
    unsigned long long r;
    asm("fma.rn.f32x2 %0, %1, %2, %3;" : "=l"(r) : "l"(a), "l"(b), "l"(c));
    return r;
}

// ---------------- 1. embedding gather -------------------------------------
__global__ void k_embed(const int* __restrict__ Z, const float* __restrict__ emb) {
    int i = blockIdx.x * blockDim.x + threadIdx.x;
    if (i < BB*NA) {
        int zi = Z[i];
        float4 e = *(const float4*)(emb + zi*4);
        *(float4*)(g_feats0 + i*4) = e;
    }
}

// ---------------- 2. radial-MLP table build (output-parallel, prefetched) --
struct CloudW {
    const float* w0; const float* b0;
    const float* w1; const float* b1;
    const float* w2; const float* b2;
    const float* w3; const float* b3;
};
struct BuildArgs { CloudW c[2]; };

__global__ void __launch_bounds__(HID + 10) k_build(BuildArgs args) {
    int cloud = blockIdx.y;
    CloudW cw = args.c[cloud];
    int t = threadIdx.x;                 // 0..159
    int tc = min(t, HID - 1);
    int pt0 = blockIdx.x * PTS;

    __shared__ float4 X0[HID + 10];
    __shared__ float4 X1[HID + 10];
    __shared__ float red[10][PTS][16];

    bool ok = (t < HID);

    float bas[PTS][3];
    const float hstep = RADIUS_F / (float)(MT - 1);
    #pragma unroll
    for (int p = 0; p < PTS; p++) {
        float r = (float)(pt0 + p) * hstep;
        #pragma unroll
        for (int j = 0; j < 3; j++) {
            float dd = (r - 1.5f * (float)j) * (1.0f / 1.5f);
            float cv = cosf(1.57079632679489662f * dd);
            bas[p][j] = (fabsf(dd) < 1.0f) ? cv * cv : 0.0f;
        }
    }

    // layer 0: 3 -> 150
    {
        float w0a = ok ? cw.w0[t]         : 0.0f;
        float w0b = ok ? cw.w0[HID + t]   : 0.0f;
        float w0c = ok ? cw.w0[2*HID + t] : 0.0f;
        float bb0 = ok ? cw.b0[t]         : 0.0f;
        float4 v;
        float* vp = (float*)&v;
        #pragma unroll
        for (int p = 0; p < PTS; p++) {
            float av = bb0;
            av = fmaf(bas[p][0], w0a, av);
            av = fmaf(bas[p][1], w0b, av);
            av = fmaf(bas[p][2], w0c, av);
            vp[p] = sp5(av);
        }
        X0[t] = v;
    }
    __syncthreads();

    // layers 1 & 2: 150 -> 150, register-prefetched weight chunks (raw layout)
    #pragma unroll
    for (int L = 0; L < 2; ++L) {
        const float* wp = (L == 0) ? cw.w1 : cw.w2;
        const float* bb = (L == 0) ? cw.b1 : cw.b2;
        const float4* S = (L == 0) ? X0 : X1;
        float4*       D = (L == 0) ? X1 : X0;

        float bv = ok ? bb[t] : 0.0f;
        float acc0 = bv, acc1 = bv, acc2 = bv, acc3 = bv;

        float wbuf[CH];
        #pragma unroll
        for (int j = 0; j < CH; j++) wbuf[j] = wp[j*HID + tc];

        for (int k0 = 0; k0 < HID; k0 += CH) {   // 15 chunks
            float wn[CH];
            bool more = (k0 + CH < HID);
            #pragma unroll
            for (int j = 0; j < CH; j++)
                wn[j] = more ? wp[(k0 + CH + j)*HID + tc] : 0.0f;
            #pragma unroll
            for (int j = 0; j < CH; j++) {
                float4 x = S[k0 + j];
                acc0 = fmaf(x.x, wbuf[j], acc0);
                acc1 = fmaf(x.y, wbuf[j], acc1);
                acc2 = fmaf(x.z, wbuf[j], acc2);
                acc3 = fmaf(x.w, wbuf[j], acc3);
            }
            #pragma unroll
            for (int j = 0; j < CH; j++) wbuf[j] = wn[j];
        }
        float4 dv;
        dv.x = sp5(acc0); dv.y = sp5(acc1); dv.z = sp5(acc2); dv.w = sp5(acc3);
        D[t] = dv;
        __syncthreads();
    }

    // layer 3: 150 -> 16, split k across 10 chunks of 15 (source is X0)
    {
        int o = t & 15, c = t >> 4;
        float a0 = 0.f, a1 = 0.f, a2 = 0.f, a3 = 0.f;
        #pragma unroll
        for (int kk = 0; kk < 15; kk++) {
            int k = c*15 + kk;
            float w = cw.w3[k*16 + o];
            float4 x = X0[k];
            a0 = fmaf(x.x, w, a0);
            a1 = fmaf(x.y, w, a1);
            a2 = fmaf(x.z, w, a2);
            a3 = fmaf(x.w, w, a3);
        }
        red[c][0][o] = a0; red[c][1][o] = a1;
        red[c][2][o] = a2; red[c][3][o] = a3;
    }
    __syncthreads();
    if (t < 16*PTS) {
        int o = t & 15, p = t >> 4;
        float s = cw.b3[o];
        #pragma unroll
        for (int c = 0; c < 10; c++) s += red[c][p][o];
        int pt = pt0 + p;
        int q = o >> 2, j = o & 3;
        g_tab2[cloud][pt*32 + q*8 + j] = s;            // this knot's k0 slot
        if (pt > 0)
            g_tab2[cloud][(pt-1)*32 + q*8 + 4 + j] = s; // previous knot's k1 slot
    }
}

// ---------------- 3. pair convolution (inline dist + table interp) --------
// grid (NAP/8, BB), 256 threads, 1 atom per warp.
// Lane = 4 channels (q) x 8 pair slots (p). Branchless: misses read the
// zero-sentinel row MT, so no gating and no divergence.
template<int CLOUD>
__global__ void __launch_bounds__(256) k_conv(const float* __restrict__ xyz) {
    int z = blockIdx.y;
    const float* feats = CLOUD ? g_f1 : g_feats0;
    float*       out   = CLOUD ? g_f2 : g_f1;
    const float* tab   = g_tab2[CLOUD];

    __shared__ float4 sc[NAP];
    __shared__ float4 sf[NAP];
    const float*  xr = xyz + (size_t)z * NA * 3;
    const float4* fz = (const float4*)(feats + (size_t)z * NA * 4);
    for (int i = threadIdx.x; i < NAP; i += 256) {
        if (i < NA) {
            sc[i] = make_float4(xr[i*3+0], xr[i*3+1], xr[i*3+2], 0.f);
            sf[i] = fz[i];
        } else {
            sc[i] = make_float4(1.0e6f, 1.0e6f, 1.0e6f, 0.f);
            sf[i] = make_float4(0.f, 0.f, 0.f, 0.f);
        }
    }
    __syncthreads();

    int warp = threadIdx.x >> 5, lane = threadIdx.x & 31;
    int q = lane & 3;        // output channel
    int p = lane >> 2;       // pair slot (0..7)
    int a = blockIdx.x * 8 + warp;
    float4 ac = sc[a];
    const float uscale = (float)(MT - 1) / RADIUS_F;
    const float* tq = tab + q*8;

    unsigned long long acc01 = 0ull, acc23 = 0ull;
    int cnt = 0;
    #pragma unroll 4
    for (int it = 0; it < NAP/8; it++) {
        int b = p + it*8;
        float4 bc = sc[b];
        float dx = ac.x - bc.x;
        float dy = ac.y - bc.y;
        float dz = ac.z - bc.z;
        float d2 = fmaf(dx, dx, fmaf(dy, dy, dz*dz));
        bool hit = (d2 < 9.0f);
        if (CLOUD == 0) cnt += hit;
        float u = hit ? fminf(sqrtf(d2) * uscale, 510.999f) : (float)MT;
        int i0 = (int)u;
        float tt = u - (float)i0;
        const float* bp = tq + i0*32;
        float4 k0 = *(const float4*)bp;
        float4 k1 = *(const float4*)(bp + 4);
        float4 f = sf[b];
        unsigned long long ttp = f2_pack(tt, tt);
        unsigned long long ssp = f2_pack(1.0f - tt, 1.0f - tt);
        // interp: kq = (1-tt)*k0 + tt*k1 ; acc += kq * f   (packed pairs)
        unsigned long long kq01 = f2_fma(*(const unsigned long long*)&k1.x, ttp,
                                         f2_mul(*(const unsigned long long*)&k0.x, ssp));
        unsigned long long kq23 = f2_fma(*(const unsigned long long*)&k1.z, ttp,
                                         f2_mul(*(const unsigned long long*)&k0.z, ssp));
        acc01 = f2_fma(kq01, *(const unsigned long long*)&f.x, acc01);
        acc23 = f2_fma(kq23, *(const unsigned long long*)&f.z, acc23);
    }
    float a0, a1, a2, a3;
    f2_unpack(a0, a1, acc01);
    f2_unpack(a2, a3, acc23);
    float acc = (a0 + a1) + (a2 + a3);

    // reduce over the 8 pair slots (lanes differing in bits 2..4)
    acc += __shfl_down_sync(0xffffffffu, acc, 16);
    acc += __shfl_down_sync(0xffffffffu, acc, 8);
    acc += __shfl_down_sync(0xffffffffu, acc, 4);
    float nb;
    if (CLOUD == 0) {
        cnt += __shfl_down_sync(0xffffffffu, cnt, 16);
        cnt += __shfl_down_sync(0xffffffffu, cnt, 8);
        cnt += __shfl_down_sync(0xffffffffu, cnt, 4);
        nb = rsqrtf((float)max(cnt, 1));
        if (a < NA && lane == 0) g_nbinv[z*NA + a] = nb;
    } else {
        nb = g_nbinv[z*NA + a];
    }
    if (a < NA && lane < 4)
        out[((size_t)z*NA + a)*4 + lane] = acc * nb;
}

// ---------------- 4. fused L2-pool + FC + softplus ------------------------
__global__ void __launch_bounds__(FF) k_poolfc(const float* __restrict__ fcw,
                                               const float* __restrict__ fcb) {
    int z = blockIdx.x;
    int lane = threadIdx.x & 31, warp = threadIdx.x >> 5;
    __shared__ float sm[16][8];
    __shared__ float spool[8];

    float s[8] = {0,0,0,0,0,0,0,0};
    for (int a = threadIdx.x; a < NA; a += FF) {
        float4 f1 = *(const float4*)(g_f1 + ((size_t)z*NA + a)*4);
        float4 f2 = *(const float4*)(g_f2 + ((size_t)z*NA + a)*4);
        s[0] += f1.x*f1.x; s[1] += f1.y*f1.y; s[2] += f1.z*f1.z; s[3] += f1.w*f1.w;
        s[4] += f2.x*f2.x; s[5] += f2.y*f2.y; s[6] += f2.z*f2.z; s[7] += f2.w*f2.w;
    }
    #pragma unroll
    for (int j = 0; j < 8; j++)
        for (int off = 16; off; off >>= 1) s[j] += __shfl_down_sync(0xffffffffu, s[j], off);
    if (lane == 0) {
        #pragma unroll
        for (int j = 0; j < 8; j++) sm[warp][j] = s[j];
    }
    __syncthreads();
    if (threadIdx.x < 8) {
        float t = 0.0f;
        #pragma unroll
        for (int w = 0; w < 16; w++) t += sm[w][threadIdx.x];
        spool[threadIdx.x] = sqrtf(t);
    }
    __syncthreads();
    int f = threadIdx.x;
    float a = fcb[f];
    #pragma unroll
    for (int c = 0; c < 8; c++) a = fmaf(spool[c], fcw[c*FF + f], a);
    g_h[z*FF + f] = softplus1(a);
}

// ---------------- 5. fused batch-stats + batchnorm + output head ----------
__global__ void __launch_bounds__(FF) k_statsout(const float* __restrict__ bng,
                                                 const float* __restrict__ bnb,
                                                 const float* __restrict__ ow,
                                                 const float* __restrict__ ob,
                                                 float* __restrict__ out) {
    int f = threadIdx.x;
    int lane = f & 31, warp = f >> 5;
    __shared__ float smw[16][BB];

    float hv[BB];
    float m = 0.0f;
    #pragma unroll
    for (int z = 0; z < BB; z++) { hv[z] = g_h[z*FF + f]; m += hv[z]; }
    m *= (1.0f / (float)BB);
    float v = 0.0f;
    #pragma unroll
    for (int z = 0; z < BB; z++) { float d = hv[z] - m; v += d*d; }
    v *= (1.0f / (float)BB);
    float sc = rsqrtf(v + 1e-5f) * bng[f];
    float bo = bnb[f];
    float w  = ow[f];

    float acc[BB];
    #pragma unroll
    for (int z = 0; z < BB; z++)
        acc[z] = softplus1((hv[z] - m) * sc + bo) * w;

    #pragma unroll
    for (int z = 0; z < BB; z++)
        for (int off = 16; off; off >>= 1)
            acc[z] += __shfl_down_sync(0xffffffffu, acc[z], off);
    if (lane == 0) {
        #pragma unroll
        for (int z = 0; z < BB; z++) smw[warp][z] = acc[z];
    }
    __syncthreads();
    if (f < BB) {
        float t = ob[0];
        #pragma unroll
        for (int wI = 0; wI < 16; wI++) t += smw[wI][f];
        out[f] = 1.0f / (1.0f + expf(-t));
    }
}

// ---------------- launch --------------------------------------------------
extern "C" void kernel_launch(void* const* d_in, const int* in_sizes, int n_in,
                              void* d_out, int out_size) {
    const float* xyz   = (const float*)d_in[0];
    const int*   Z     = (const int*)  d_in[1];
    const float* emb   = (const float*)d_in[2];
    const float* c0_w0 = (const float*)d_in[3];
    const float* c0_b0 = (const float*)d_in[4];
    const float* c0_w1 = (const float*)d_in[5];
    const float* c0_b1 = (const float*)d_in[6];
    const float* c0_w2 = (const float*)d_in[7];
    const float* c0_b2 = (const float*)d_in[8];
    const float* c0_w3 = (const float*)d_in[9];
    const float* c0_b3 = (const float*)d_in[10];
    const float* c1_w0 = (const float*)d_in[11];
    const float* c1_b0 = (const float*)d_in[12];
    const float* c1_w1 = (const float*)d_in[13];
    const float* c1_b1 = (const float*)d_in[14];
    const float* c1_w2 = (const float*)d_in[15];
    const float* c1_b2 = (const float*)d_in[16];
    const float* c1_w3 = (const float*)d_in[17];
    const float* c1_b3 = (const float*)d_in[18];
    const float* fc_w  = (const float*)d_in[19];
    const float* fc_b  = (const float*)d_in[20];
    const float* bn_g  = (const float*)d_in[21];
    const float* bn_b  = (const float*)d_in[22];
    const float* out_w = (const float*)d_in[23];
    const float* out_b = (const float*)d_in[24];
    float* out = (float*)d_out;

    k_embed<<<(BB*NA + 255) / 256, 256>>>(Z, emb);

    BuildArgs ba;
    ba.c[0].w0 = c0_w0; ba.c[0].b0 = c0_b0; ba.c[0].w1 = c0_w1; ba.c[0].b1 = c0_b1;
    ba.c[0].w2 = c0_w2; ba.c[0].b2 = c0_b2; ba.c[0].w3 = c0_w3; ba.c[0].b3 = c0_b3;
    ba.c[1].w0 = c1_w0; ba.c[1].b0 = c1_b0; ba.c[1].w1 = c1_w1; ba.c[1].b1 = c1_b1;
    ba.c[1].w2 = c1_w2; ba.c[1].b2 = c1_b2; ba.c[1].w3 = c1_w3; ba.c[1].b3 = c1_b3;
    k_build<<<dim3(MT / PTS, 2), HID + 10>>>(ba);

    dim3 cg(NAP / 8, BB);
    k_conv<0><<<cg, 256>>>(xyz);
    k_conv<1><<<cg, 256>>>(xyz);
    k_poolfc<<<BB, FF>>>(fc_w, fc_b);
    k_statsout<<<1, FF>>>(bn_g, bn_b, out_w, out_b, out);
}

// round 11
// speedup vs baseline: 1.7072x; 1.7072x over previous
#include <cuda_runtime.h>
#include <math.h>

#define BB      16
#define NA      286
#define NAP     288       // padded atom count (multiple of 8)
#define HID     150
#define FF      512
#define RADIUS_F 3.0f
#define MT      256       // table knots per cloud
#define PTS     4         // points per build block
#define CH      10        // k-chunk (prefetch depth) in build

// ---------------- scratch (device globals; no allocation allowed) ----------
__device__ __align__(16) float g_feats0[BB*NA*4];
__device__ __align__(16) float g_f1[BB*NA*4];
__device__ __align__(16) float g_f2[BB*NA*4];
// paired-knot table: row i holds {K_i[q][0..3], K_{i+1}[q][0..3]} for q=0..3
// -> 32 floats = 128 B per row (both knots in one cache line).
__device__ __align__(16) float g_tab2[2][MT*32];
__device__ float g_nbinv[BB*NA];
__device__ float g_h[BB*FF];

__device__ __forceinline__ float sp5(float x) {
    float z = 5.0f * x;
    return (fmaxf(z, 0.0f) + log1pf(expf(-fabsf(z)))) * 0.2f;
}
__device__ __forceinline__ float softplus1(float x) {
    return fmaxf(x, 0.0f) + log1pf(expf(-fabsf(x)));
}

// ---------------- 1. embedding gather -------------------------------------
__global__ void k_embed(const int* __restrict__ Z, const float* __restrict__ emb) {
    int i = blockIdx.x * blockDim.x + threadIdx.x;
    if (i < BB*NA) {
        int zi = Z[i];
        float4 e = *(const float4*)(emb + zi*4);
        *(float4*)(g_feats0 + i*4) = e;
    }
}

// ---------------- 2. radial-MLP table build (output-parallel, prefetched) --
struct CloudW {
    const float* w0; const float* b0;
    const float* w1; const float* b1;
    const float* w2; const float* b2;
    const float* w3; const float* b3;
};
struct BuildArgs { CloudW c[2]; };

__global__ void __launch_bounds__(HID + 10) k_build(BuildArgs args) {
    int cloud = blockIdx.y;
    CloudW cw = args.c[cloud];
    int t = threadIdx.x;                 // 0..159
    int tc = min(t, HID - 1);
    int pt0 = blockIdx.x * PTS;

    __shared__ float4 X0[HID + 10];
    __shared__ float4 X1[HID + 10];
    __shared__ float red[10][PTS][16];

    bool ok = (t < HID);

    float bas[PTS][3];
    const float hstep = RADIUS_F / (float)(MT - 1);
    #pragma unroll
    for (int p = 0; p < PTS; p++) {
        float r = (float)(pt0 + p) * hstep;
        #pragma unroll
        for (int j = 0; j < 3; j++) {
            float dd = (r - 1.5f * (float)j) * (1.0f / 1.5f);
            float cv = cosf(1.57079632679489662f * dd);
            bas[p][j] = (fabsf(dd) < 1.0f) ? cv * cv : 0.0f;
        }
    }

    // layer 0: 3 -> 150
    {
        float w0a = ok ? cw.w0[t]         : 0.0f;
        float w0b = ok ? cw.w0[HID + t]   : 0.0f;
        float w0c = ok ? cw.w0[2*HID + t] : 0.0f;
        float bb0 = ok ? cw.b0[t]         : 0.0f;
        float4 v;
        float* vp = (float*)&v;
        #pragma unroll
        for (int p = 0; p < PTS; p++) {
            float av = bb0;
            av = fmaf(bas[p][0], w0a, av);
            av = fmaf(bas[p][1], w0b, av);
            av = fmaf(bas[p][2], w0c, av);
            vp[p] = sp5(av);
        }
        X0[t] = v;
    }
    __syncthreads();

    // layers 1 & 2: 150 -> 150, register-prefetched weight chunks (raw layout)
    #pragma unroll
    for (int L = 0; L < 2; ++L) {
        const float* wp = (L == 0) ? cw.w1 : cw.w2;
        const float* bb = (L == 0) ? cw.b1 : cw.b2;
        const float4* S = (L == 0) ? X0 : X1;
        float4*       D = (L == 0) ? X1 : X0;

        float bv = ok ? bb[t] : 0.0f;
        float acc0 = bv, acc1 = bv, acc2 = bv, acc3 = bv;

        float wbuf[CH];
        #pragma unroll
        for (int j = 0; j < CH; j++) wbuf[j] = wp[j*HID + tc];

        for (int k0 = 0; k0 < HID; k0 += CH) {   // 15 chunks
            float wn[CH];
            bool more = (k0 + CH < HID);
            #pragma unroll
            for (int j = 0; j < CH; j++)
                wn[j] = more ? wp[(k0 + CH + j)*HID + tc] : 0.0f;
            #pragma unroll
            for (int j = 0; j < CH; j++) {
                float4 x = S[k0 + j];
                acc0 = fmaf(x.x, wbuf[j], acc0);
                acc1 = fmaf(x.y, wbuf[j], acc1);
                acc2 = fmaf(x.z, wbuf[j], acc2);
                acc3 = fmaf(x.w, wbuf[j], acc3);
            }
            #pragma unroll
            for (int j = 0; j < CH; j++) wbuf[j] = wn[j];
        }
        float4 dv;
        dv.x = sp5(acc0); dv.y = sp5(acc1); dv.z = sp5(acc2); dv.w = sp5(acc3);
        D[t] = dv;
        __syncthreads();
    }

    // layer 3: 150 -> 16, split k across 10 chunks of 15 (source is X0)
    {
        int o = t & 15, c = t >> 4;
        float a0 = 0.f, a1 = 0.f, a2 = 0.f, a3 = 0.f;
        #pragma unroll
        for (int kk = 0; kk < 15; kk++) {
            int k = c*15 + kk;
            float w = cw.w3[k*16 + o];
            float4 x = X0[k];
            a0 = fmaf(x.x, w, a0);
            a1 = fmaf(x.y, w, a1);
            a2 = fmaf(x.z, w, a2);
            a3 = fmaf(x.w, w, a3);
        }
        red[c][0][o] = a0; red[c][1][o] = a1;
        red[c][2][o] = a2; red[c][3][o] = a3;
    }
    __syncthreads();
    if (t < 16*PTS) {
        int o = t & 15, p = t >> 4;
        float s = cw.b3[o];
        #pragma unroll
        for (int c = 0; c < 10; c++) s += red[c][p][o];
        int pt = pt0 + p;
        int q = o >> 2, j = o & 3;
        g_tab2[cloud][pt*32 + q*8 + j] = s;            // this knot's k0 slot
        if (pt > 0)
            g_tab2[cloud][(pt-1)*32 + q*8 + 4 + j] = s; // previous knot's k1 slot
    }
}

// ---------------- 3. pair convolution (inline dist + table interp) --------
// grid (NAP/8, BB), 256 threads, 1 atom per warp (R7 structure).
// Lane = 4 channels (q) x 8 pair slots (p). Dot-first interpolation:
// contribution = (K_i0 . f) + tt * ((K_i0+1 . f) - (K_i0 . f)).
template<int CLOUD>
__global__ void __launch_bounds__(256) k_conv(const float* __restrict__ xyz) {
    int z = blockIdx.y;
    const float* feats = CLOUD ? g_f1 : g_feats0;
    float*       out   = CLOUD ? g_f2 : g_f1;
    const float* tab   = g_tab2[CLOUD];

    __shared__ float4 sc[NAP];
    __shared__ float4 sf[NAP];
    const float*  xr = xyz + (size_t)z * NA * 3;
    const float4* fz = (const float4*)(feats + (size_t)z * NA * 4);
    for (int i = threadIdx.x; i < NAP; i += 256) {
        if (i < NA) {
            sc[i] = make_float4(xr[i*3+0], xr[i*3+1], xr[i*3+2], 0.f);
            sf[i] = fz[i];
        } else {
            sc[i] = make_float4(1.0e6f, 1.0e6f, 1.0e6f, 0.f);
            sf[i] = make_float4(0.f, 0.f, 0.f, 0.f);
        }
    }
    __syncthreads();

    int warp = threadIdx.x >> 5, lane = threadIdx.x & 31;
    int q = lane & 3;        // output channel
    int p = lane >> 2;       // pair slot (0..7)
    int a = blockIdx.x * 8 + warp;
    float4 ac = sc[a];
    const float uscale = (float)(MT - 1) / RADIUS_F;
    const float* tq = tab + q*8;

    float acc = 0.0f;
    int cnt = 0;
    #pragma unroll 4
    for (int it = 0; it < NAP/8; it++) {
        int b = p + it*8;
        float4 bc = sc[b];
        float dx = ac.x - bc.x;
        float dy = ac.y - bc.y;
        float dz = ac.z - bc.z;
        float d2 = fmaf(dx, dx, fmaf(dy, dy, dz*dz));
        if (d2 < 9.0f) {
            if (CLOUD == 0) cnt++;
            float u = fminf(sqrtf(d2) * uscale, (float)(MT - 1) - 1e-3f);
            int i0 = (int)u;
            float tt = u - (float)i0;
            const float* bp = tq + i0*32;
            float4 k0 = *(const float4*)bp;
            float4 k1 = *(const float4*)(bp + 4);
            float4 f = sf[b];
            float s0 = k0.x*f.x;
            s0 = fmaf(k0.y, f.y, s0);
            s0 = fmaf(k0.z, f.z, s0);
            s0 = fmaf(k0.w, f.w, s0);
            float s1 = k1.x*f.x;
            s1 = fmaf(k1.y, f.y, s1);
            s1 = fmaf(k1.z, f.z, s1);
            s1 = fmaf(k1.w, f.w, s1);
            acc += fmaf(tt, s1 - s0, s0);
        }
    }
    // reduce over the 8 pair slots (lanes differing in bits 2..4)
    acc += __shfl_down_sync(0xffffffffu, acc, 16);
    acc += __shfl_down_sync(0xffffffffu, acc, 8);
    acc += __shfl_down_sync(0xffffffffu, acc, 4);
    float nb;
    if (CLOUD == 0) {
        cnt += __shfl_down_sync(0xffffffffu, cnt, 16);
        cnt += __shfl_down_sync(0xffffffffu, cnt, 8);
        cnt += __shfl_down_sync(0xffffffffu, cnt, 4);
        nb = rsqrtf((float)max(cnt, 1));
        if (a < NA && lane == 0) g_nbinv[z*NA + a] = nb;
    } else {
        nb = g_nbinv[z*NA + a];
    }
    if (a < NA && lane < 4)
        out[((size_t)z*NA + a)*4 + lane] = acc * nb;
}

// ---------------- 4. fused L2-pool + FC + softplus ------------------------
__global__ void __launch_bounds__(FF) k_poolfc(const float* __restrict__ fcw,
                                               const float* __restrict__ fcb) {
    int z = blockIdx.x;
    int lane = threadIdx.x & 31, warp = threadIdx.x >> 5;
    __shared__ float sm[16][8];
    __shared__ float spool[8];

    float s[8] = {0,0,0,0,0,0,0,0};
    for (int a = threadIdx.x; a < NA; a += FF) {
        float4 f1 = *(const float4*)(g_f1 + ((size_t)z*NA + a)*4);
        float4 f2 = *(const float4*)(g_f2 + ((size_t)z*NA + a)*4);
        s[0] += f1.x*f1.x; s[1] += f1.y*f1.y; s[2] += f1.z*f1.z; s[3] += f1.w*f1.w;
        s[4] += f2.x*f2.x; s[5] += f2.y*f2.y; s[6] += f2.z*f2.z; s[7] += f2.w*f2.w;
    }
    #pragma unroll
    for (int j = 0; j < 8; j++)
        for (int off = 16; off; off >>= 1) s[j] += __shfl_down_sync(0xffffffffu, s[j], off);
    if (lane == 0) {
        #pragma unroll
        for (int j = 0; j < 8; j++) sm[warp][j] = s[j];
    }
    __syncthreads();
    if (threadIdx.x < 8) {
        float t = 0.0f;
        #pragma unroll
        for (int w = 0; w < 16; w++) t += sm[w][threadIdx.x];
        spool[threadIdx.x] = sqrtf(t);
    }
    __syncthreads();
    int f = threadIdx.x;
    float a = fcb[f];
    #pragma unroll
    for (int c = 0; c < 8; c++) a = fmaf(spool[c], fcw[c*FF + f], a);
    g_h[z*FF + f] = softplus1(a);
}

// ---------------- 5. fused batch-stats + batchnorm + output head ----------
__global__ void __launch_bounds__(FF) k_statsout(const float* __restrict__ bng,
                                                 const float* __restrict__ bnb,
                                                 const float* __restrict__ ow,
                                                 const float* __restrict__ ob,
                                                 float* __restrict__ out) {
    int f = threadIdx.x;
    int lane = f & 31, warp = f >> 5;
    __shared__ float smw[16][BB];

    float hv[BB];
    float m = 0.0f;
    #pragma unroll
    for (int z = 0; z < BB; z++) { hv[z] = g_h[z*FF + f]; m += hv[z]; }
    m *= (1.0f / (float)BB);
    float v = 0.0f;
    #pragma unroll
    for (int z = 0; z < BB; z++) { float d = hv[z] - m; v += d*d; }
    v *= (1.0f / (float)BB);
    float sc = rsqrtf(v + 1e-5f) * bng[f];
    float bo = bnb[f];
    float w  = ow[f];

    float acc[BB];
    #pragma unroll
    for (int z = 0; z < BB; z++)
        acc[z] = softplus1((hv[z] - m) * sc + bo) * w;

    #pragma unroll
    for (int z = 0; z < BB; z++)
        for (int off = 16; off; off >>= 1)
            acc[z] += __shfl_down_sync(0xffffffffu, acc[z], off);
    if (lane == 0) {
        #pragma unroll
        for (int z = 0; z < BB; z++) smw[warp][z] = acc[z];
    }
    __syncthreads();
    if (f < BB) {
        float t = ob[0];
        #pragma unroll
        for (int wI = 0; wI < 16; wI++) t += smw[wI][f];
        out[f] = 1.0f / (1.0f + expf(-t));
    }
}

// ---------------- launch --------------------------------------------------
extern "C" void kernel_launch(void* const* d_in, const int* in_sizes, int n_in,
                              void* d_out, int out_size) {
    const float* xyz   = (const float*)d_in[0];
    const int*   Z     = (const int*)  d_in[1];
    const float* emb   = (const float*)d_in[2];
    const float* c0_w0 = (const float*)d_in[3];
    const float* c0_b0 = (const float*)d_in[4];
    const float* c0_w1 = (const float*)d_in[5];
    const float* c0_b1 = (const float*)d_in[6];
    const float* c0_w2 = (const float*)d_in[7];
    const float* c0_b2 = (const float*)d_in[8];
    const float* c0_w3 = (const float*)d_in[9];
    const float* c0_b3 = (const float*)d_in[10];
    const float* c1_w0 = (const float*)d_in[11];
    const float* c1_b0 = (const float*)d_in[12];
    const float* c1_w1 = (const float*)d_in[13];
    const float* c1_b1 = (const float*)d_in[14];
    const float* c1_w2 = (const float*)d_in[15];
    const float* c1_b2 = (const float*)d_in[16];
    const float* c1_w3 = (const float*)d_in[17];
    const float* c1_b3 = (const float*)d_in[18];
    const float* fc_w  = (const float*)d_in[19];
    const float* fc_b  = (const float*)d_in[20];
    const float* bn_g  = (const float*)d_in[21];
    const float* bn_b  = (const float*)d_in[22];
    const float* out_w = (const float*)d_in[23];
    const float* out_b = (const float*)d_in[24];
    float* out = (float*)d_out;

    k_embed<<<(BB*NA + 255) / 256, 256>>>(Z, emb);

    BuildArgs ba;
    ba.c[0].w0 = c0_w0; ba.c[0].b0 = c0_b0; ba.c[0].w1 = c0_w1; ba.c[0].b1 = c0_b1;
    ba.c[0].w2 = c0_w2; ba.c[0].b2 = c0_b2; ba.c[0].w3 = c0_w3; ba.c[0].b3 = c0_b3;
    ba.c[1].w0 = c1_w0; ba.c[1].b0 = c1_b0; ba.c[1].w1 = c1_w1; ba.c[1].b1 = c1_b1;
    ba.c[1].w2 = c1_w2; ba.c[1].b2 = c1_b2; ba.c[1].w3 = c1_w3; ba.c[1].b3 = c1_b3;
    k_build<<<dim3(MT / PTS, 2), HID + 10>>>(ba);

    dim3 cg(NAP / 8, BB);
    k_conv<0><<<cg, 256>>>(xyz);
    k_conv<1><<<cg, 256>>>(xyz);
    k_poolfc<<<BB, FF>>>(fc_w, fc_b);
    k_statsout<<<1, FF>>>(bn_g, bn_b, out_w, out_b, out);
}